// round 2
// baseline (speedup 1.0000x reference)
#include <cuda_runtime.h>
#include <math.h>

// Problem constants
#define K_EMB   1024
#define D_EMB   256
#define N_VEC   65536          // 4 * 16 * 32 * 32
#define DHW     16384          // 16*32*32
#define ZQ_ELEMS (N_VEC * D_EMB)   // 16777216
#define LOSS_OFF ZQ_ELEMS
#define IDX_OFF  (ZQ_ELEMS + 1)
#define PERP_OFF (ZQ_ELEMS + 1 + N_VEC)

// Scratch (static device globals: no allocation allowed)
__device__ float g_eT[D_EMB * K_EMB];     // transposed embedding [d][k]
__device__ float g_enorm[K_EMB];          // ||e_k||^2 (sequential fp32 sum)
__device__ float g_xnorm[N_VEC];          // ||x_n||^2 (sequential fp32 sum)
__device__ int   g_idx[N_VEC];            // argmin indices
__device__ int   g_hist[K_EMB];           // assignment histogram
__device__ float g_partial[16384];        // per-block loss partial sums

// ---------------------------------------------------------------------------
// init: zero histogram
__global__ void vq_init_kernel() {
    g_hist[threadIdx.x] = 0;
}

// ---------------------------------------------------------------------------
// prep: eT[d][k] = e[k][d]
__global__ void vq_prep_kernel(const float* __restrict__ emb) {
    int k = blockIdx.x;
    int t = threadIdx.x;            // 256 threads, one per d
    float v = emb[k * D_EMB + t];
    g_eT[t * K_EMB + k] = v;
}

// enorm[k] = sequential in-order fp32 sum of fl(e^2), matching XLA CPU reduce
__global__ void vq_enorm_kernel(const float* __restrict__ emb) {
    int k = blockIdx.x * blockDim.x + threadIdx.x;   // 1024 threads
    const float* row = emb + (size_t)k * D_EMB;
    float acc = 0.0f;
    for (int d = 0; d < D_EMB; d++) {
        float sq = __fmul_rn(row[d], row[d]);
        acc = __fadd_rn(acc, sq);
    }
    g_enorm[k] = acc;
}

// xnorm[n] = sequential in-order fp32 sum of fl(z^2) over channel dim.
// One thread per flat row n = b*DHW + dhw; channel stride = DHW (coalesced over n).
__global__ void vq_xnorm_kernel(const float* __restrict__ z) {
    int n = blockIdx.x * blockDim.x + threadIdx.x;
    int b = n >> 14;
    int dhw = n & 16383;
    const float* p = z + (size_t)b * D_EMB * DHW + dhw;
    float acc = 0.0f;
    for (int c = 0; c < D_EMB; c++) {
        float v = p[(size_t)c * DHW];
        float sq = __fmul_rn(v, v);
        acc = __fadd_rn(acc, sq);
    }
    g_xnorm[n] = acc;
}

// ---------------------------------------------------------------------------
// Fused distance-GEMM + row argmin, with reference-faithful fp32 epilogue:
//   s = fl( fl(xnorm + enorm) - 2*dot ),  ties -> lowest k.
// Block: 256 threads (16x16 logical), tile 64 rows x 64 cols, 4x4 micro-tile.
__global__ void __launch_bounds__(256, 2)
vq_argmin_kernel(const float* __restrict__ z) {
    extern __shared__ float smem[];
    float* As = smem;               // 256*64
    float* Bs = smem + 256 * 64;    // 32*64

    int tid = threadIdx.x;
    int tx = tid & 15;              // col group (4 cols)
    int ty = tid >> 4;              // row group (4 rows)

    int rowBase = blockIdx.x * 64;          // multiple of 64, never crosses b
    int b       = rowBase >> 14;
    int dhwBase = rowBase & 16383;
    const float* zb = z + (size_t)b * D_EMB * DHW + dhwBase;

    // Load z tile: As[c*64 + r] = z[b, c, dhwBase + r]  (coalesced over r)
    for (int i = tid; i < 256 * 64; i += 256) {
        int c = i >> 6, r = i & 63;
        As[i] = zb[(size_t)c * DHW + r];
    }

    // xnorm for my 4 rows
    float xn[4];
    #pragma unroll
    for (int i = 0; i < 4; i++) xn[i] = g_xnorm[rowBase + ty * 4 + i];

    float minv[4] = {1e30f, 1e30f, 1e30f, 1e30f};
    int   mini[4] = {0, 0, 0, 0};

    for (int kt = 0; kt < 16; kt++) {
        int k0 = kt * 64;
        float acc[4][4];
        #pragma unroll
        for (int i = 0; i < 4; i++)
            #pragma unroll
            for (int j = 0; j < 4; j++) acc[i][j] = 0.0f;

        for (int dc = 0; dc < 8; dc++) {
            int d0 = dc * 32;
            __syncthreads();
            // stage Bs[d][k] from eT (coalesced over k)
            for (int i = tid; i < 32 * 64; i += 256) {
                int d = i >> 6, kk = i & 63;
                Bs[i] = g_eT[(size_t)(d0 + d) * K_EMB + k0 + kk];
            }
            __syncthreads();
            #pragma unroll
            for (int d = 0; d < 32; d++) {
                float4 a  = *(const float4*)&As[(d0 + d) * 64 + ty * 4];
                float4 bv = *(const float4*)&Bs[d * 64 + tx * 4];
                float ar[4] = {a.x, a.y, a.z, a.w};
                float br[4] = {bv.x, bv.y, bv.z, bv.w};
                #pragma unroll
                for (int i = 0; i < 4; i++)
                    #pragma unroll
                    for (int j = 0; j < 4; j++)
                        acc[i][j] += ar[i] * br[j];
            }
        }
        // epilogue for this K-tile: s = fl(fl(xn + en) - 2*dot), no FMA contraction
        #pragma unroll
        for (int j = 0; j < 4; j++) {
            int k = k0 + tx * 4 + j;
            float en = g_enorm[k];
            #pragma unroll
            for (int i = 0; i < 4; i++) {
                float t1 = __fadd_rn(xn[i], en);
                float c2 = __fmul_rn(-2.0f, acc[i][j]);   // exact
                float s  = __fadd_rn(t1, c2);
                if (s < minv[i]) { minv[i] = s; mini[i] = k; }  // k ascending
            }
        }
    }

    // Cross-thread reduction over the 16 tx threads sharing each row.
    __syncthreads();
    float* redV = Bs;                       // 64*16 floats
    int*   redI = (int*)(Bs + 64 * 16);     // 64*16 ints
    #pragma unroll
    for (int i = 0; i < 4; i++) {
        int row = ty * 4 + i;
        redV[row * 16 + tx] = minv[i];
        redI[row * 16 + tx] = mini[i];
    }
    __syncthreads();
    if (tid < 64) {
        float bv = redV[tid * 16];
        int   bi = redI[tid * 16];
        #pragma unroll
        for (int t = 1; t < 16; t++) {
            float v  = redV[tid * 16 + t];
            int   id = redI[tid * 16 + t];
            if (v < bv || (v == bv && id < bi)) { bv = v; bi = id; }
        }
        g_idx[rowBase + tid] = bi;
    }
}

// ---------------------------------------------------------------------------
// Gather z_q back to (B, C, Dd, H, W) layout + per-block loss partials.
__global__ void vq_gather_kernel(const float* __restrict__ z,
                                 const float* __restrict__ emb,
                                 float* __restrict__ out) {
    __shared__ float tile[32][33];
    __shared__ int   idxs[32];
    __shared__ float red[256];

    int nBase = blockIdx.x * 32;
    int cBase = blockIdx.y * 32;
    int tx = threadIdx.x, ty = threadIdx.y;
    int tid = ty * 32 + tx;

    if (tid < 32) idxs[tid] = g_idx[nBase + tid];
    __syncthreads();

    #pragma unroll
    for (int i = 0; i < 4; i++) {
        int nl = ty + 8 * i;
        tile[tx][nl] = emb[(size_t)idxs[nl] * D_EMB + cBase + tx];
    }
    __syncthreads();

    int b   = nBase >> 14;
    int dhw = (nBase & 16383) + tx;
    float lsum = 0.0f;
    #pragma unroll
    for (int i = 0; i < 4; i++) {
        int cl = ty + 8 * i;
        size_t off = ((size_t)(b * D_EMB + cBase + cl)) * DHW + dhw;
        float q  = tile[cl][tx];
        float zv = z[off];
        out[off] = q;                    // straight-through forward == z_q
        float d  = zv - q;
        lsum += d * d;
    }

    red[tid] = lsum;
    __syncthreads();
    #pragma unroll
    for (int s = 128; s > 0; s >>= 1) {
        if (tid < s) red[tid] += red[tid + s];
        __syncthreads();
    }
    if (tid == 0) g_partial[blockIdx.x * gridDim.y + blockIdx.y] = red[0];
}

// ---------------------------------------------------------------------------
// indices output (as float) + histogram
__global__ void vq_idx_kernel(float* __restrict__ out) {
    int n = blockIdx.x * blockDim.x + threadIdx.x;
    int id = g_idx[n];
    out[IDX_OFF + n] = (float)id;
    atomicAdd(&g_hist[id], 1);
}

// ---------------------------------------------------------------------------
// finalize: vq_loss (deterministic tree over partials) + perplexity
__global__ void vq_finalize_kernel(float* __restrict__ out) {
    __shared__ float red[1024];
    int t = threadIdx.x;

    float s = 0.0f;
    #pragma unroll
    for (int i = 0; i < 16; i++) s += g_partial[t * 16 + i];
    red[t] = s;
    __syncthreads();
    #pragma unroll
    for (int st = 512; st > 0; st >>= 1) {
        if (t < st) red[t] += red[t + st];
        __syncthreads();
    }
    if (t == 0) out[LOSS_OFF] = 0.25f * red[0] / (float)ZQ_ELEMS;
    __syncthreads();

    float p = (float)g_hist[t] * (1.0f / (float)N_VEC);
    red[t] = p * logf(p + 1e-10f);
    __syncthreads();
    #pragma unroll
    for (int st = 512; st > 0; st >>= 1) {
        if (t < st) red[t] += red[t + st];
        __syncthreads();
    }
    if (t == 0) out[PERP_OFF] = expf(-red[0]);
}

// ---------------------------------------------------------------------------
extern "C" void kernel_launch(void* const* d_in, const int* in_sizes, int n_in,
                              void* d_out, int out_size) {
    const float* z   = (const float*)d_in[0];
    const float* emb = (const float*)d_in[1];
    if (in_sizes[0] == K_EMB * D_EMB) {
        const float* t = z; z = emb; emb = t;
    }
    float* out = (float*)d_out;

    const int SMEM_BYTES = (256 * 64 + 32 * 64) * sizeof(float);  // 73728
    cudaFuncSetAttribute(vq_argmin_kernel,
                         cudaFuncAttributeMaxDynamicSharedMemorySize, SMEM_BYTES);

    vq_init_kernel<<<1, K_EMB>>>();
    vq_prep_kernel<<<K_EMB, D_EMB>>>(emb);
    vq_enorm_kernel<<<4, 256>>>(emb);
    vq_xnorm_kernel<<<N_VEC / 256, 256>>>(z);
    vq_argmin_kernel<<<N_VEC / 64, 256, SMEM_BYTES>>>(z);

    dim3 ggrid(N_VEC / 32, D_EMB / 32);
    dim3 gblk(32, 8);
    vq_gather_kernel<<<ggrid, gblk>>>(z, emb, out);

    vq_idx_kernel<<<N_VEC / 1024, 1024>>>(out);
    vq_finalize_kernel<<<1, 1024>>>(out);
}

// round 7
// speedup vs baseline: 1.7797x; 1.7797x over previous
#include <cuda_runtime.h>
#include <cuda_bf16.h>
#include <math.h>
#include <stdint.h>

// Problem constants
#define K_EMB   1024
#define D_EMB   256
#define N_VEC   65536          // 4 * 16 * 32 * 32
#define DHW     16384          // 16*32*32
#define ZQ_ELEMS (N_VEC * D_EMB)
#define LOSS_OFF ZQ_ELEMS
#define IDX_OFF  (ZQ_ELEMS + 1)
#define PERP_OFF (ZQ_ELEMS + 1 + N_VEC)

#define TAU 2e-3f

// ---------------------------------------------------------------------------
// Static device scratch (no runtime allocation allowed)
__device__ __nv_bfloat16 g_zh[N_VEC * D_EMB];   // z high bf16, [n][d]
__device__ float         g_zT[N_VEC * D_EMB];   // z fp32 transposed, [n][d]
__device__ __nv_bfloat16 g_eh[K_EMB * D_EMB];   // emb high bf16, [k][d]
__device__ float g_enorm[K_EMB];
__device__ float g_xnorm[N_VEC];
__device__ int   g_idx[N_VEC];
__device__ int   g_hist[K_EMB];
__device__ float g_partial[16384];

// ---------------------------------------------------------------------------
static __device__ __forceinline__ uint32_t s2u(const void* p) {
    uint32_t a;
    asm("{ .reg .u64 t; cvta.to.shared.u64 t, %1; cvt.u32.u64 %0, t; }"
        : "=r"(a) : "l"(p));
    return a;
}
static __device__ __forceinline__ void ldsm_x4(uint32_t* r, uint32_t addr) {
    asm volatile("ldmatrix.sync.aligned.m8n8.x4.shared.b16 {%0,%1,%2,%3}, [%4];"
        : "=r"(r[0]), "=r"(r[1]), "=r"(r[2]), "=r"(r[3]) : "r"(addr));
}
static __device__ __forceinline__ void mma16816(float* d, const uint32_t* a,
                                                const uint32_t* b) {
    asm volatile(
        "mma.sync.aligned.m16n8k16.row.col.f32.bf16.bf16.f32 "
        "{%0,%1,%2,%3}, {%4,%5,%6,%7}, {%8,%9}, {%0,%1,%2,%3};"
        : "+f"(d[0]), "+f"(d[1]), "+f"(d[2]), "+f"(d[3])
        : "r"(a[0]), "r"(a[1]), "r"(a[2]), "r"(a[3]), "r"(b[0]), "r"(b[1]));
}

// smem layout for topk kernel (bytes). Rows padded to 528B => LDSM conflict-free.
#define ROW_PITCH 528
#define SM_A     0                         // 128 x 528 = 67584
#define SM_B     67584                     // 64 x 528  = 33792
#define SM_EN    101376                    // 1024 f32  = 4096
#define SM_CAND  105472                    // 128*64 u16 = 16384
#define SM_CNT   121856                    // 128 u32   = 512
#define SM_TOTAL 122368

// ---------------------------------------------------------------------------
__global__ void vq_init_kernel() { g_hist[threadIdx.x] = 0; }

// enorm[k]: sequential in-order fp32 sum of fl(e^2)
__global__ void vq_enorm_kernel(const float* __restrict__ emb) {
    int k = blockIdx.x * blockDim.x + threadIdx.x;
    const float* row = emb + (size_t)k * D_EMB;
    float acc = 0.0f;
    for (int d = 0; d < D_EMB; d++) {
        float sq = __fmul_rn(row[d], row[d]);
        acc = __fadd_rn(acc, sq);
    }
    g_enorm[k] = acc;
}

// xnorm[n]: sequential in-order fp32 sum over channel dim
__global__ void vq_xnorm_kernel(const float* __restrict__ z) {
    int n = blockIdx.x * blockDim.x + threadIdx.x;
    int b = n >> 14;
    int dhw = n & 16383;
    const float* p = z + (size_t)b * D_EMB * DHW + dhw;
    float acc = 0.0f;
    for (int c = 0; c < D_EMB; c++) {
        float v = p[(size_t)c * DHW];
        float sq = __fmul_rn(v, v);
        acc = __fadd_rn(acc, sq);
    }
    g_xnorm[n] = acc;
}

// bf16 high part of embedding
__global__ void vq_split_e_kernel(const float* __restrict__ emb) {
    int i = blockIdx.x * blockDim.x + threadIdx.x;
    g_eh[i] = __float2bfloat16(emb[i]);
}

// transpose z (b,c,dhw) -> [n][d]: fp32 copy + bf16 high part
__global__ void vq_split_z_kernel(const float* __restrict__ z) {
    __shared__ float tile[32][33];
    int nBase = blockIdx.x * 32;
    int cBase = blockIdx.y * 32;
    int tx = threadIdx.x, ty = threadIdx.y;
    int b = nBase >> 14;
    int dhw = (nBase & 16383) + tx;

    #pragma unroll
    for (int i = 0; i < 4; i++) {
        int cl = ty + 8 * i;
        tile[cl][tx] = z[((size_t)(b * D_EMB + cBase + cl)) * DHW + dhw];
    }
    __syncthreads();
    #pragma unroll
    for (int i = 0; i < 4; i++) {
        int nl = ty + 8 * i;
        float v = tile[tx][nl];
        int o = (nBase + nl) * D_EMB + cBase + tx;
        g_zT[o] = v;
        g_zh[o] = __float2bfloat16(v);
    }
}

// ---------------------------------------------------------------------------
// Fused: bf16 mma.sync filter (approx scores, candidate collection) +
//        exact fp32 rescore with reference-faithful epilogue.
// CTA: 128 rows x all 1024 codes; 8 warps, warp w owns rows w*16..w*16+15.
__global__ void __launch_bounds__(256, 1)
vq_topk_kernel(const float* __restrict__ emb) {
    extern __shared__ char sm[];
    uint32_t sb = s2u(sm);
    float*          sEn   = (float*)(sm + SM_EN);
    unsigned short* sCand = (unsigned short*)(sm + SM_CAND);
    unsigned int*   sCnt  = (unsigned int*)(sm + SM_CNT);

    int tid  = threadIdx.x;
    int wid  = tid >> 5;
    int lane = tid & 31;
    int rowBase = blockIdx.x * 128;

    if (tid < 128) sCnt[tid] = 0;
    for (int i = tid; i < K_EMB; i += 256) sEn[i] = g_enorm[i];

    // Stage A tile: 128 rows x 256 d bf16 (512B payload, 528B pitch)
    {
        const __nv_bfloat16* za = g_zh + (size_t)rowBase * D_EMB;
        for (int i = tid; i < 4096; i += 256) {
            int r = i >> 5, c = i & 31;
            *(uint4*)(sm + SM_A + r * ROW_PITCH + c * 16) =
                *(const uint4*)(za + (size_t)r * D_EMB + c * 8);
        }
    }
    __syncthreads();

    // Load A fragments into registers: 16 k-fragments x 4 regs
    uint32_t afrag[16][4];
    {
        uint32_t base = sb + SM_A + (wid * 16 + (lane & 15)) * ROW_PITCH
                      + (lane >> 4) * 16;
        #pragma unroll
        for (int kf = 0; kf < 16; kf++) ldsm_x4(afrag[kf], base + kf * 32);
    }

    int r0loc = wid * 16 + (lane >> 2);     // row of d0/d1; d2/d3 = r0loc+8
    float run0 = 1e30f, run1 = 1e30f;

    for (int chunk = 0; chunk < 16; chunk++) {
        __syncthreads();
        // Stage B: 64 codes x 256 d bf16
        const __nv_bfloat16* eb = g_eh + (size_t)(chunk * 64) * D_EMB;
        for (int i = tid; i < 2048; i += 256) {
            int r = i >> 5, c = i & 31;
            *(uint4*)(sm + SM_B + r * ROW_PITCH + c * 16) =
                *(const uint4*)(eb + (size_t)r * D_EMB + c * 8);
        }
        __syncthreads();

        for (int t = 0; t < 8; t++) {
            int kb = chunk * 64 + t * 8;
            float d4[4] = {0.f, 0.f, 0.f, 0.f};
            uint32_t bbase = sb + SM_B + (t * 8 + (lane & 7)) * ROW_PITCH
                           + (lane >> 3) * 16;
            #pragma unroll
            for (int kf2 = 0; kf2 < 8; kf2++) {
                uint32_t b[4];
                ldsm_x4(b, bbase + kf2 * 64);
                mma16816(d4, afrag[2 * kf2],     b);
                mma16816(d4, afrag[2 * kf2 + 1], b + 2);
            }
            // epilogue: approx scores, quad-synced running min, candidate push
            int c0 = kb + (lane & 3) * 2;
            float en0 = sEn[c0], en1 = sEn[c0 + 1];
            float s0 = en0 - 2.0f * d4[0];
            float s1 = en1 - 2.0f * d4[1];
            float s2 = en0 - 2.0f * d4[2];
            float s3 = en1 - 2.0f * d4[3];

            float m0 = fminf(s0, s1), m1 = fminf(s2, s3);
            m0 = fminf(m0, __shfl_xor_sync(0xFFFFFFFFu, m0, 1));
            m0 = fminf(m0, __shfl_xor_sync(0xFFFFFFFFu, m0, 2));
            m1 = fminf(m1, __shfl_xor_sync(0xFFFFFFFFu, m1, 1));
            m1 = fminf(m1, __shfl_xor_sync(0xFFFFFFFFu, m1, 2));
            run0 = fminf(run0, m0);
            run1 = fminf(run1, m1);

            if (s0 < run0 + TAU) {
                unsigned slot = atomicAdd(&sCnt[r0loc], 1u);
                if (slot < 64) sCand[r0loc * 64 + slot] = (unsigned short)c0;
            }
            if (s1 < run0 + TAU) {
                unsigned slot = atomicAdd(&sCnt[r0loc], 1u);
                if (slot < 64) sCand[r0loc * 64 + slot] = (unsigned short)(c0 + 1);
            }
            if (s2 < run1 + TAU) {
                unsigned slot = atomicAdd(&sCnt[r0loc + 8], 1u);
                if (slot < 64) sCand[(r0loc + 8) * 64 + slot] = (unsigned short)c0;
            }
            if (s3 < run1 + TAU) {
                unsigned slot = atomicAdd(&sCnt[r0loc + 8], 1u);
                if (slot < 64) sCand[(r0loc + 8) * 64 + slot] = (unsigned short)(c0 + 1);
            }
        }
    }
    __syncthreads();

    // Rescore: exact fp32 dot per candidate, reference-faithful score,
    // lexicographic (s, k) argmin. Warp w handles rows w, w+8, ...
    for (int rl = wid; rl < 128; rl += 8) {
        int n = rowBase + rl;
        float xn = g_xnorm[n];
        const float* zr = g_zT + (size_t)n * D_EMB;
        float4 za = *(const float4*)(zr + lane * 4);
        float4 zb = *(const float4*)(zr + 128 + lane * 4);

        unsigned cnt = sCnt[rl];
        int num = (cnt <= 64u) ? (int)cnt : K_EMB;
        float best = 1e30f;
        int bestk = K_EMB;
        for (int i = 0; i < num; i++) {
            int k = (cnt <= 64u) ? (int)sCand[rl * 64 + i] : i;
            const float* er = emb + (size_t)k * D_EMB;
            float4 ea = *(const float4*)(er + lane * 4);
            float4 eb4 = *(const float4*)(er + 128 + lane * 4);
            float dot = za.x * ea.x;
            dot = fmaf(za.y, ea.y, dot);
            dot = fmaf(za.z, ea.z, dot);
            dot = fmaf(za.w, ea.w, dot);
            dot = fmaf(zb.x, eb4.x, dot);
            dot = fmaf(zb.y, eb4.y, dot);
            dot = fmaf(zb.z, eb4.z, dot);
            dot = fmaf(zb.w, eb4.w, dot);
            #pragma unroll
            for (int m = 16; m > 0; m >>= 1)
                dot += __shfl_xor_sync(0xFFFFFFFFu, dot, m);
            float s = __fadd_rn(__fadd_rn(xn, sEn[k]), __fmul_rn(-2.0f, dot));
            if (s < best || (s == best && k < bestk)) { best = s; bestk = k; }
        }
        if (lane == 0) g_idx[n] = bestk;
    }
}

// ---------------------------------------------------------------------------
// Gather z_q back to (B, C, Dd, H, W) + per-block loss partials (R2-proven)
__global__ void vq_gather_kernel(const float* __restrict__ z,
                                 const float* __restrict__ emb,
                                 float* __restrict__ out) {
    __shared__ float tile[32][33];
    __shared__ int   idxs[32];
    __shared__ float red[256];

    int nBase = blockIdx.x * 32;
    int cBase = blockIdx.y * 32;
    int tx = threadIdx.x, ty = threadIdx.y;
    int tid = ty * 32 + tx;

    if (tid < 32) idxs[tid] = g_idx[nBase + tid];
    __syncthreads();

    #pragma unroll
    for (int i = 0; i < 4; i++) {
        int nl = ty + 8 * i;
        tile[tx][nl] = emb[(size_t)idxs[nl] * D_EMB + cBase + tx];
    }
    __syncthreads();

    int b   = nBase >> 14;
    int dhw = (nBase & 16383) + tx;
    float lsum = 0.0f;
    #pragma unroll
    for (int i = 0; i < 4; i++) {
        int cl = ty + 8 * i;
        size_t off = ((size_t)(b * D_EMB + cBase + cl)) * DHW + dhw;
        float q  = tile[cl][tx];
        float zv = z[off];
        out[off] = q;
        float d  = zv - q;
        lsum += d * d;
    }

    red[tid] = lsum;
    __syncthreads();
    #pragma unroll
    for (int s = 128; s > 0; s >>= 1) {
        if (tid < s) red[tid] += red[tid + s];
        __syncthreads();
    }
    if (tid == 0) g_partial[blockIdx.x * gridDim.y + blockIdx.y] = red[0];
}

__global__ void vq_idx_kernel(float* __restrict__ out) {
    int n = blockIdx.x * blockDim.x + threadIdx.x;
    int id = g_idx[n];
    out[IDX_OFF + n] = (float)id;
    atomicAdd(&g_hist[id], 1);
}

__global__ void vq_finalize_kernel(float* __restrict__ out) {
    __shared__ float red[1024];
    int t = threadIdx.x;

    float s = 0.0f;
    #pragma unroll
    for (int i = 0; i < 16; i++) s += g_partial[t * 16 + i];
    red[t] = s;
    __syncthreads();
    #pragma unroll
    for (int st = 512; st > 0; st >>= 1) {
        if (t < st) red[t] += red[t + st];
        __syncthreads();
    }
    if (t == 0) out[LOSS_OFF] = 0.25f * red[0] / (float)ZQ_ELEMS;
    __syncthreads();

    float p = (float)g_hist[t] * (1.0f / (float)N_VEC);
    red[t] = p * logf(p + 1e-10f);
    __syncthreads();
    #pragma unroll
    for (int st = 512; st > 0; st >>= 1) {
        if (t < st) red[t] += red[t + st];
        __syncthreads();
    }
    if (t == 0) out[PERP_OFF] = expf(-red[0]);
}

// ---------------------------------------------------------------------------
extern "C" void kernel_launch(void* const* d_in, const int* in_sizes, int n_in,
                              void* d_out, int out_size) {
    const float* z   = (const float*)d_in[0];
    const float* emb = (const float*)d_in[1];
    if (in_sizes[0] == K_EMB * D_EMB) {
        const float* t = z; z = emb; emb = t;
    }
    float* out = (float*)d_out;

    cudaFuncSetAttribute(vq_topk_kernel,
                         cudaFuncAttributeMaxDynamicSharedMemorySize, SM_TOTAL);

    vq_init_kernel<<<1, K_EMB>>>();
    vq_enorm_kernel<<<4, 256>>>(emb);
    vq_xnorm_kernel<<<N_VEC / 256, 256>>>(z);
    vq_split_e_kernel<<<K_EMB * D_EMB / 256, 256>>>(emb);

    dim3 sgrid(N_VEC / 32, D_EMB / 32);
    dim3 sblk(32, 8);
    vq_split_z_kernel<<<sgrid, sblk>>>(z);

    vq_topk_kernel<<<N_VEC / 128, 256, SM_TOTAL>>>(emb);

    vq_gather_kernel<<<sgrid, sblk>>>(z, emb, out);
    vq_idx_kernel<<<N_VEC / 1024, 1024>>>(out);
    vq_finalize_kernel<<<1, 1024>>>(out);
}

// round 8
// speedup vs baseline: 2.2161x; 1.2452x over previous
#include <cuda_runtime.h>
#include <cuda_bf16.h>
#include <math.h>
#include <stdint.h>

// Problem constants
#define K_EMB   1024
#define D_EMB   256
#define N_VEC   65536          // 4 * 16 * 32 * 32
#define DHW     16384          // 16*32*32
#define ZQ_ELEMS (N_VEC * D_EMB)
#define LOSS_OFF ZQ_ELEMS
#define IDX_OFF  (ZQ_ELEMS + 1)
#define PERP_OFF (ZQ_ELEMS + 1 + N_VEC)

#define TAU 2e-3f

// ---------------------------------------------------------------------------
// Static device scratch (no runtime allocation allowed)
__device__ __nv_bfloat16 g_zh[N_VEC * D_EMB];   // z high bf16, [n][d]
__device__ float         g_zT[N_VEC * D_EMB];   // z fp32 transposed, [n][d]
__device__ __nv_bfloat16 g_eh[K_EMB * D_EMB];   // emb high bf16, [k][d]
__device__ float g_enorm[K_EMB];
__device__ float g_xnorm[N_VEC];
__device__ int   g_idx[N_VEC];
__device__ int   g_hist[K_EMB];
__device__ float g_partial[16384];

// ---------------------------------------------------------------------------
static __device__ __forceinline__ uint32_t s2u(const void* p) {
    uint32_t a;
    asm("{ .reg .u64 t; cvta.to.shared.u64 t, %1; cvt.u32.u64 %0, t; }"
        : "=r"(a) : "l"(p));
    return a;
}
static __device__ __forceinline__ void ldsm_x4(uint32_t* r, uint32_t addr) {
    asm volatile("ldmatrix.sync.aligned.m8n8.x4.shared.b16 {%0,%1,%2,%3}, [%4];"
        : "=r"(r[0]), "=r"(r[1]), "=r"(r[2]), "=r"(r[3]) : "r"(addr));
}
static __device__ __forceinline__ void mma16816(float* d, const uint32_t* a,
                                                const uint32_t* b) {
    asm volatile(
        "mma.sync.aligned.m16n8k16.row.col.f32.bf16.bf16.f32 "
        "{%0,%1,%2,%3}, {%4,%5,%6,%7}, {%8,%9}, {%0,%1,%2,%3};"
        : "+f"(d[0]), "+f"(d[1]), "+f"(d[2]), "+f"(d[3])
        : "r"(a[0]), "r"(a[1]), "r"(a[2]), "r"(a[3]), "r"(b[0]), "r"(b[1]));
}
#define CP_ASYNC16(s, g) \
    asm volatile("cp.async.cg.shared.global [%0], [%1], 16;" \
        :: "r"(s), "l"(g) : "memory")
#define CP_COMMIT() asm volatile("cp.async.commit_group;" ::: "memory")
#define CP_WAIT(n)  asm volatile("cp.async.wait_group %0;" :: "n"(n) : "memory")

// smem layout (bytes). Rows padded to 528B => LDSM conflict-free (528%128==16).
#define ROW_PITCH 528
#define SM_A     0                         // 128 x 528 = 67584
#define SM_B0    67584                     // 64 x 528  = 33792
#define SM_B1    101376                    // 64 x 528  = 33792
#define SM_EN    135168                    // 1024 f32  = 4096
#define SM_CAND  139264                    // 128*64 u16 = 16384
#define SM_CNT   155648                    // 128 u32   = 512
#define SM_TOTAL 156160

// ---------------------------------------------------------------------------
__global__ void vq_init_kernel() { g_hist[threadIdx.x] = 0; }

// enorm[k]: sequential in-order fp32 sum of fl(e^2)
__global__ void vq_enorm_kernel(const float* __restrict__ emb) {
    int k = blockIdx.x * blockDim.x + threadIdx.x;
    const float* row = emb + (size_t)k * D_EMB;
    float acc = 0.0f;
    for (int d = 0; d < D_EMB; d++) {
        float sq = __fmul_rn(row[d], row[d]);
        acc = __fadd_rn(acc, sq);
    }
    g_enorm[k] = acc;
}

// xnorm[n]: sequential in-order fp32 sum over channel dim
__global__ void vq_xnorm_kernel(const float* __restrict__ z) {
    int n = blockIdx.x * blockDim.x + threadIdx.x;
    int b = n >> 14;
    int dhw = n & 16383;
    const float* p = z + (size_t)b * D_EMB * DHW + dhw;
    float acc = 0.0f;
    for (int c = 0; c < D_EMB; c++) {
        float v = p[(size_t)c * DHW];
        float sq = __fmul_rn(v, v);
        acc = __fadd_rn(acc, sq);
    }
    g_xnorm[n] = acc;
}

// bf16 high part of embedding
__global__ void vq_split_e_kernel(const float* __restrict__ emb) {
    int i = blockIdx.x * blockDim.x + threadIdx.x;
    g_eh[i] = __float2bfloat16(emb[i]);
}

// transpose z (b,c,dhw) -> [n][d]: fp32 copy + bf16 high part
__global__ void vq_split_z_kernel(const float* __restrict__ z) {
    __shared__ float tile[32][33];
    int nBase = blockIdx.x * 32;
    int cBase = blockIdx.y * 32;
    int tx = threadIdx.x, ty = threadIdx.y;
    int b = nBase >> 14;
    int dhw = (nBase & 16383) + tx;

    #pragma unroll
    for (int i = 0; i < 4; i++) {
        int cl = ty + 8 * i;
        tile[cl][tx] = z[((size_t)(b * D_EMB + cBase + cl)) * DHW + dhw];
    }
    __syncthreads();
    #pragma unroll
    for (int i = 0; i < 4; i++) {
        int nl = ty + 8 * i;
        float v = tile[tx][nl];
        int o = (nBase + nl) * D_EMB + cBase + tx;
        g_zT[o] = v;
        g_zh[o] = __float2bfloat16(v);
    }
}

// ---------------------------------------------------------------------------
// Fused: bf16 mma.sync filter + exact fp32 rescore.
// CTA: 128 rows x 1024 codes; cp.async double-buffered B; dual accumulators;
// deferred (per-chunk) min-reduce + candidate sweep.
__global__ void __launch_bounds__(256, 1)
vq_topk_kernel(const float* __restrict__ emb) {
    extern __shared__ char sm[];
    uint32_t sb = s2u(sm);
    float*          sEn   = (float*)(sm + SM_EN);
    unsigned short* sCand = (unsigned short*)(sm + SM_CAND);
    unsigned int*   sCnt  = (unsigned int*)(sm + SM_CNT);

    int tid  = threadIdx.x;
    int wid  = tid >> 5;
    int lane = tid & 31;
    int rowBase = blockIdx.x * 128;

    // Stage A tile (cp.async): 128 rows x 512B payload
    {
        const __nv_bfloat16* za = g_zh + (size_t)rowBase * D_EMB;
        #pragma unroll
        for (int j = 0; j < 16; j++) {
            int i = tid + j * 256;                 // 4096 chunks of 16B
            int r = i >> 5, c = i & 31;
            CP_ASYNC16(sb + SM_A + r * ROW_PITCH + c * 16,
                       (const char*)(za + (size_t)r * D_EMB + c * 8));
        }
        CP_COMMIT();
    }
    // Prefetch B chunk 0 into B0
    {
        const __nv_bfloat16* eb = g_eh;
        #pragma unroll
        for (int j = 0; j < 8; j++) {
            int i = tid + j * 256;                 // 2048 chunks of 16B
            int r = i >> 5, c = i & 31;
            CP_ASYNC16(sb + SM_B0 + r * ROW_PITCH + c * 16,
                       (const char*)(eb + (size_t)r * D_EMB + c * 8));
        }
        CP_COMMIT();
    }

    if (tid < 128) sCnt[tid] = 0;
    for (int i = tid; i < K_EMB; i += 256) sEn[i] = g_enorm[i];

    CP_WAIT(1);                  // A complete (B0 may still be in flight)
    __syncthreads();

    // A fragments: 16 k-fragments x 4 regs (validated R7 addressing)
    uint32_t afrag[16][4];
    {
        uint32_t base = sb + SM_A + (wid * 16 + (lane & 15)) * ROW_PITCH
                      + (lane >> 4) * 16;
        #pragma unroll
        for (int kf = 0; kf < 16; kf++) ldsm_x4(afrag[kf], base + kf * 32);
    }

    int r0loc = wid * 16 + (lane >> 2);     // row of s0/s1; s2/s3 -> r0loc+8
    float run0 = 1e30f, run1 = 1e30f;

    for (int chunk = 0; chunk < 16; chunk++) {
        uint32_t bufC = (chunk & 1) ? SM_B1 : SM_B0;
        // prefetch next chunk into the other buffer
        if (chunk < 15) {
            uint32_t bufN = (chunk & 1) ? SM_B0 : SM_B1;
            const __nv_bfloat16* eb = g_eh + (size_t)((chunk + 1) * 64) * D_EMB;
            #pragma unroll
            for (int j = 0; j < 8; j++) {
                int i = tid + j * 256;
                int r = i >> 5, c = i & 31;
                CP_ASYNC16(sb + bufN + r * ROW_PITCH + c * 16,
                           (const char*)(eb + (size_t)r * D_EMB + c * 8));
            }
            CP_COMMIT();
            CP_WAIT(1);          // current chunk's data complete
        } else {
            CP_WAIT(0);
        }
        __syncthreads();

        float sc[32];            // buffered scores: [2t], [2t+1] row r0loc; [16+..] r0loc+8
        float m0 = 1e30f, m1 = 1e30f;

        #pragma unroll
        for (int t = 0; t < 8; t++) {
            int kb = chunk * 64 + t * 8;
            float d4a[4] = {0.f, 0.f, 0.f, 0.f};
            float d4b[4] = {0.f, 0.f, 0.f, 0.f};
            uint32_t bbase = sb + bufC + (t * 8 + (lane & 7)) * ROW_PITCH
                           + (lane >> 3) * 16;
            uint32_t bp[4], bq[4];
            ldsm_x4(bp, bbase);
            #pragma unroll
            for (int kf2 = 0; kf2 < 8; kf2++) {
                uint32_t* bc = (kf2 & 1) ? bq : bp;
                uint32_t* bn = (kf2 & 1) ? bp : bq;
                if (kf2 < 7) ldsm_x4(bn, bbase + (kf2 + 1) * 64);
                mma16816(d4a, afrag[2 * kf2],     bc);      // independent
                mma16816(d4b, afrag[2 * kf2 + 1], bc + 2);  // accumulators
            }
            int c0 = kb + (lane & 3) * 2;
            float en0 = sEn[c0], en1 = sEn[c0 + 1];
            float s0 = en0 - 2.0f * (d4a[0] + d4b[0]);
            float s1 = en1 - 2.0f * (d4a[1] + d4b[1]);
            float s2 = en0 - 2.0f * (d4a[2] + d4b[2]);
            float s3 = en1 - 2.0f * (d4a[3] + d4b[3]);
            sc[2 * t] = s0; sc[2 * t + 1] = s1;
            sc[16 + 2 * t] = s2; sc[16 + 2 * t + 1] = s3;
            m0 = fminf(m0, fminf(s0, s1));
            m1 = fminf(m1, fminf(s2, s3));
        }

        // per-chunk quad reduce + running min update (off MMA critical path)
        m0 = fminf(m0, __shfl_xor_sync(0xFFFFFFFFu, m0, 1));
        m0 = fminf(m0, __shfl_xor_sync(0xFFFFFFFFu, m0, 2));
        m1 = fminf(m1, __shfl_xor_sync(0xFFFFFFFFu, m1, 1));
        m1 = fminf(m1, __shfl_xor_sync(0xFFFFFFFFu, m1, 2));
        run0 = fminf(run0, m0);
        run1 = fminf(run1, m1);

        // candidate sweep (rarely taken branches)
        float th0 = run0 + TAU, th1 = run1 + TAU;
        #pragma unroll
        for (int j = 0; j < 16; j++) {
            int code = chunk * 64 + (j >> 1) * 8 + (lane & 3) * 2 + (j & 1);
            if (sc[j] < th0) {
                unsigned slot = atomicAdd(&sCnt[r0loc], 1u);
                if (slot < 64) sCand[r0loc * 64 + slot] = (unsigned short)code;
            }
            if (sc[16 + j] < th1) {
                unsigned slot = atomicAdd(&sCnt[r0loc + 8], 1u);
                if (slot < 64) sCand[(r0loc + 8) * 64 + slot] = (unsigned short)code;
            }
        }
        __syncthreads();         // done reading bufC before it is re-staged
    }
    __syncthreads();

    // Rescore: exact fp32 dot per candidate, reference-faithful score,
    // lexicographic (s, k) argmin. Warp w handles rows w, w+8, ...
    for (int rl = wid; rl < 128; rl += 8) {
        int n = rowBase + rl;
        float xn = g_xnorm[n];
        const float* zr = g_zT + (size_t)n * D_EMB;
        float4 za = *(const float4*)(zr + lane * 4);
        float4 zb = *(const float4*)(zr + 128 + lane * 4);

        unsigned cnt = sCnt[rl];
        int num = (cnt <= 64u) ? (int)cnt : K_EMB;
        float best = 1e30f;
        int bestk = K_EMB;
        for (int i = 0; i < num; i++) {
            int k = (cnt <= 64u) ? (int)sCand[rl * 64 + i] : i;
            const float* er = emb + (size_t)k * D_EMB;
            float4 ea = *(const float4*)(er + lane * 4);
            float4 eb4 = *(const float4*)(er + 128 + lane * 4);
            float dot = za.x * ea.x;
            dot = fmaf(za.y, ea.y, dot);
            dot = fmaf(za.z, ea.z, dot);
            dot = fmaf(za.w, ea.w, dot);
            dot = fmaf(zb.x, eb4.x, dot);
            dot = fmaf(zb.y, eb4.y, dot);
            dot = fmaf(zb.z, eb4.z, dot);
            dot = fmaf(zb.w, eb4.w, dot);
            #pragma unroll
            for (int m = 16; m > 0; m >>= 1)
                dot += __shfl_xor_sync(0xFFFFFFFFu, dot, m);
            float s = __fadd_rn(__fadd_rn(xn, sEn[k]), __fmul_rn(-2.0f, dot));
            if (s < best || (s == best && k < bestk)) { best = s; bestk = k; }
        }
        if (lane == 0) g_idx[n] = bestk;
    }
}

// ---------------------------------------------------------------------------
// Gather z_q back to (B, C, Dd, H, W) + per-block loss partials
__global__ void vq_gather_kernel(const float* __restrict__ z,
                                 const float* __restrict__ emb,
                                 float* __restrict__ out) {
    __shared__ float tile[32][33];
    __shared__ int   idxs[32];
    __shared__ float red[256];

    int nBase = blockIdx.x * 32;
    int cBase = blockIdx.y * 32;
    int tx = threadIdx.x, ty = threadIdx.y;
    int tid = ty * 32 + tx;

    if (tid < 32) idxs[tid] = g_idx[nBase + tid];
    __syncthreads();

    #pragma unroll
    for (int i = 0; i < 4; i++) {
        int nl = ty + 8 * i;
        tile[tx][nl] = emb[(size_t)idxs[nl] * D_EMB + cBase + tx];
    }
    __syncthreads();

    int b   = nBase >> 14;
    int dhw = (nBase & 16383) + tx;
    float lsum = 0.0f;
    #pragma unroll
    for (int i = 0; i < 4; i++) {
        int cl = ty + 8 * i;
        size_t off = ((size_t)(b * D_EMB + cBase + cl)) * DHW + dhw;
        float q  = tile[cl][tx];
        float zv = z[off];
        out[off] = q;
        float d  = zv - q;
        lsum += d * d;
    }

    red[tid] = lsum;
    __syncthreads();
    #pragma unroll
    for (int s = 128; s > 0; s >>= 1) {
        if (tid < s) red[tid] += red[tid + s];
        __syncthreads();
    }
    if (tid == 0) g_partial[blockIdx.x * gridDim.y + blockIdx.y] = red[0];
}

__global__ void vq_idx_kernel(float* __restrict__ out) {
    int n = blockIdx.x * blockDim.x + threadIdx.x;
    int id = g_idx[n];
    out[IDX_OFF + n] = (float)id;
    atomicAdd(&g_hist[id], 1);
}

__global__ void vq_finalize_kernel(float* __restrict__ out) {
    __shared__ float red[1024];
    int t = threadIdx.x;

    float s = 0.0f;
    #pragma unroll
    for (int i = 0; i < 16; i++) s += g_partial[t * 16 + i];
    red[t] = s;
    __syncthreads();
    #pragma unroll
    for (int st = 512; st > 0; st >>= 1) {
        if (t < st) red[t] += red[t + st];
        __syncthreads();
    }
    if (t == 0) out[LOSS_OFF] = 0.25f * red[0] / (float)ZQ_ELEMS;
    __syncthreads();

    float p = (float)g_hist[t] * (1.0f / (float)N_VEC);
    red[t] = p * logf(p + 1e-10f);
    __syncthreads();
    #pragma unroll
    for (int st = 512; st > 0; st >>= 1) {
        if (t < st) red[t] += red[t + st];
        __syncthreads();
    }
    if (t == 0) out[PERP_OFF] = expf(-red[0]);
}

// ---------------------------------------------------------------------------
extern "C" void kernel_launch(void* const* d_in, const int* in_sizes, int n_in,
                              void* d_out, int out_size) {
    const float* z   = (const float*)d_in[0];
    const float* emb = (const float*)d_in[1];
    if (in_sizes[0] == K_EMB * D_EMB) {
        const float* t = z; z = emb; emb = t;
    }
    float* out = (float*)d_out;

    cudaFuncSetAttribute(vq_topk_kernel,
                         cudaFuncAttributeMaxDynamicSharedMemorySize, SM_TOTAL);

    vq_init_kernel<<<1, K_EMB>>>();
    vq_enorm_kernel<<<4, 256>>>(emb);
    vq_xnorm_kernel<<<N_VEC / 256, 256>>>(z);
    vq_split_e_kernel<<<K_EMB * D_EMB / 256, 256>>>(emb);

    dim3 sgrid(N_VEC / 32, D_EMB / 32);
    dim3 sblk(32, 8);
    vq_split_z_kernel<<<sgrid, sblk>>>(z);

    vq_topk_kernel<<<N_VEC / 128, 256, SM_TOTAL>>>(emb);

    vq_gather_kernel<<<sgrid, sblk>>>(z, emb, out);
    vq_idx_kernel<<<N_VEC / 1024, 1024>>>(out);
    vq_finalize_kernel<<<1, 1024>>>(out);
}